// round 15
// baseline (speedup 1.0000x reference)
#include <cuda_runtime.h>
#include <cuda_bf16.h>
#include <math_constants.h>

// ShiftNMF fused single-kernel:
//   Hft = FFT(softplus(H)) computed by CTAs 0..15 (one row each),
//   published via device flag; all CTAs then compute
//   out[n,m] = Re( sum_d softplus(W[n,d]) * exp(-2*pi*i*tau[n,d]*m/M) * Hft[d,m] ).
// Output float32 = Re(V), out_size = N*M.

#define N_ROWS 1024
#define RANK   16
#define M_LEN  4096
#define LOG2M  12

__device__ float2   g_Hft[RANK * M_LEN];
__device__ unsigned g_fft_done;    // zero-init; reset by last CTA each run
__device__ unsigned g_reset_ctr;   // zero-init; reset by last CTA each run

__device__ __forceinline__ float softplus_accurate(float x) {
    return (x > 20.0f) ? x : log1pf(expf(x));
}
__device__ __forceinline__ float2 cmul(float2 a, float2 b) {
    return make_float2(a.x * b.x - a.y * b.y, a.x * b.y + a.y * b.x);
}
__device__ __forceinline__ unsigned long long pack2(float lo, float hi) {
    unsigned long long r;
    asm("mov.b64 %0, {%1, %2};" : "=l"(r) : "f"(lo), "f"(hi));
    return r;
}
__device__ __forceinline__ void unpack2(unsigned long long v, float& lo, float& hi) {
    asm("mov.b64 {%0, %1}, %2;" : "=f"(lo), "=f"(hi) : "l"(v));
}
#define FMA2(dst, a, b, c) \
    asm("fma.rn.f32x2 %0, %1, %2, %3;" : "=l"(dst) : "l"(a), "l"(b), "l"(c))

__device__ __forceinline__ unsigned ld_acquire_u32(const unsigned* p) {
    unsigned v;
    asm volatile("ld.global.acquire.gpu.u32 %0, [%1];" : "=r"(v) : "l"(p));
    return v;
}

// ---------------------------------------------------------------------------
#define THREADS 128
#define CHUNK_M 512
#define M_ITERS (CHUNK_M / 32)            // 16
#define ROWS_W  2
#define WARPS_PER_CTA 4
#define ROWS_CTA (WARPS_PER_CTA * ROWS_W) // 8
#define GRID_MX (M_LEN / CHUNK_M)         // 8
#define GRID_NY (N_ROWS / ROWS_CTA)       // 128
#define GRID    (GRID_MX * GRID_NY)       // 1024 CTAs
#define TWO_PI  6.28318530717958647692f

__global__ void __launch_bounds__(THREADS, 5) shiftnmf_fused_kernel(
    const float* __restrict__ H,
    const float* __restrict__ W,
    const float* __restrict__ tau,
    float* __restrict__ out,
    unsigned long long max_elems)
{
    __shared__ float2 buf[M_LEN];                // 32 KB (FFT CTAs only)
    __shared__ float4 tb[ROWS_CTA * RANK];       // 2 KB seed table

    const int tid  = threadIdx.x;
    const int lane = tid & 31;
    const int warp = tid >> 5;
    const int bid  = blockIdx.x;

    // ---------------- Phase 1: CTAs 0..15 compute one FFT row each ----------
    if (bid < RANK) {
        const int row = bid;
        // Base-4 digit-reversed load of softplus(H[row, i]).
        for (int i = tid; i < M_LEN; i += THREADS) {
            unsigned r = __brev((unsigned)i) >> (32 - LOG2M);
            r = ((r & 0x555u) << 1) | ((r >> 1) & 0x555u);
            float v = softplus_accurate(H[row * M_LEN + i]);
            buf[r] = make_float2(v, 0.0f);
        }
        __syncthreads();

        // 6 radix-4 stages, 8 butterflies/thread/stage, inline twiddles.
        #pragma unroll 1
        for (int s = 1; s <= 6; s++) {
            const int q = 1 << (2 * (s - 1));
            const float astep = -TWO_PI / (float)(4 * q);
            for (int j = tid; j < M_LEN / 4; j += THREADS) {
                int k    = j & (q - 1);
                int g    = j >> (2 * (s - 1));
                int base = g * (q << 2) + k;

                float a1 = astep * (float)k;
                float s1, c1, s2, c2;
                __sincosf(a1, &s1, &c1);
                __sincosf(a1 + a1, &s2, &c2);
                float2 w1 = make_float2(c1, s1);
                float2 w2 = make_float2(c2, s2);
                float2 w3 = cmul(w1, w2);

                float2 y0 = buf[base];
                float2 y1 = buf[base + q];
                float2 y2 = buf[base + 2 * q];
                float2 y3 = buf[base + 3 * q];

                float2 t1 = cmul(w1, y1);
                float2 t2 = cmul(w2, y2);
                float2 t3 = cmul(w3, y3);

                float2 u0 = make_float2(y0.x + t2.x, y0.y + t2.y);
                float2 u1 = make_float2(y0.x - t2.x, y0.y - t2.y);
                float2 u2 = make_float2(t1.x + t3.x, t1.y + t3.y);
                float2 u3 = make_float2(t1.x - t3.x, t1.y - t3.y);

                buf[base]         = make_float2(u0.x + u2.x, u0.y + u2.y);
                buf[base + 2 * q] = make_float2(u0.x - u2.x, u0.y - u2.y);
                buf[base + q]     = make_float2(u1.x + u3.y, u1.y - u3.x);
                buf[base + 3 * q] = make_float2(u1.x - u3.y, u1.y + u3.x);
            }
            __syncthreads();
        }

        for (int i = tid; i < M_LEN; i += THREADS) {
            g_Hft[row * M_LEN + i] = buf[i];
        }
        __threadfence();          // publish this thread's g_Hft stores
        __syncthreads();          // all threads' stores fenced
        if (tid == 0) atomicAdd(&g_fft_done, 1u);
    }

    // ---------------- Phase 2: every CTA computes an 8-row x 512-m tile -----
    const int mx     = bid & (GRID_MX - 1);
    const int ny     = bid >> 3;
    const int m_base = mx * CHUNK_M;
    const int nblk   = ny * ROWS_CTA;

    // Seed table: 128 entries (8 rows x 16 d), one thread each.
    {
        const int rl = tid >> 4;
        const int d  = tid & 15;
        const int n  = nblk + rl;
        float t  = tau[n * RANK + d];
        float sw = softplus_accurate(W[n * RANK + d]);
        float ss, cs;
        sincospif(-t * (64.0f / (float)M_LEN), &ss, &cs);   // 32-step angle
        tb[rl * RANK + d] = make_float4(sw, -TWO_PI * t / (float)M_LEN, cs, ss);
    }

    // Wait for all 16 FFT rows (producers are in wave 1: bids 0..15).
    if (tid == 0) {
        while (ld_acquire_u32(&g_fft_done) < (unsigned)RANK) {
            __nanosleep(128);
        }
    }
    __syncthreads();   // releases CTA; also publishes tb

    unsigned long long acc2[ROWS_W][M_ITERS];
    #pragma unroll
    for (int r = 0; r < ROWS_W; r++)
        #pragma unroll
        for (int i = 0; i < M_ITERS; i++) acc2[r][i] = 0ULL;

    const float fm0 = (float)(m_base + lane);
    const float2* __restrict__ hp = g_Hft + m_base + lane;

    #pragma unroll 1
    for (int d = 0; d < RANK; d++) {
        // Seed packed rotators (2 rows, this d) from the smem table.
        unsigned long long A2[ROWS_W], B2[ROWS_W], KP2[ROWS_W], KN2[ROWS_W];
        #pragma unroll
        for (int r = 0; r < ROWS_W; r++) {
            float4 e = tb[(warp * ROWS_W + r) * RANK + d];
            float s0, c0;
            __sincosf(e.y * fm0, &s0, &c0);
            float cr = e.x * c0;
            float ci = e.x * s0;
            float k  = e.z + e.z;
            A2[r]  = pack2(cr, ci);
            B2[r]  = pack2(-fmaf(cr, e.z,  ci * e.w),
                            fmaf(cr, e.w, -ci * e.z));
            KP2[r] = pack2(k, k);
            KN2[r] = pack2(-k, -k);
        }

        const float2* __restrict__ hd = hp + d * M_LEN;

        #pragma unroll
        for (int it = 0; it < M_ITERS; it++) {
            unsigned long long h2 =
                *reinterpret_cast<const unsigned long long*>(&hd[it * 32]);
            #pragma unroll
            for (int r = 0; r < ROWS_W; r++) {
                if ((it & 1) == 0) {
                    FMA2(acc2[r][it], A2[r], h2, acc2[r][it]);
                    FMA2(B2[r], KP2[r], A2[r], B2[r]);
                } else {
                    FMA2(acc2[r][it], B2[r], h2, acc2[r][it]);
                    FMA2(A2[r], KN2[r], B2[r], A2[r]);
                }
            }
        }
    }

    #pragma unroll
    for (int r = 0; r < ROWS_W; r++) {
        const unsigned long long row_base =
            (unsigned long long)(nblk + warp * ROWS_W + r) * M_LEN + m_base;
        #pragma unroll
        for (int it = 0; it < M_ITERS; it++) {
            float ax, ay;
            unpack2(acc2[r][it], ax, ay);
            float val = ((it & 2) == 0) ? (ax - ay) : (ay - ax);
            unsigned long long fi = row_base + (unsigned long long)(it * 32 + lane);
            if (fi < max_elems) out[fi] = val;
        }
    }

    // ---------------- Reset flags for the next (graph-replayed) run --------
    __syncthreads();
    if (tid == 0) {
        unsigned prev = atomicAdd(&g_reset_ctr, 1u);
        if (prev == (unsigned)(GRID - 1)) {
            g_fft_done  = 0u;
            g_reset_ctr = 0u;
            __threadfence();
        }
    }
}

// ---------------------------------------------------------------------------
extern "C" void kernel_launch(void* const* d_in, const int* in_sizes, int n_in,
                              void* d_out, int out_size) {
    // H = strictly largest input; remaining two in given order = W, tau_tilde.
    int hi = 0;
    for (int i = 1; i < n_in; i++)
        if (in_sizes[i] > in_sizes[hi]) hi = i;

    const float* H = (const float*)d_in[hi];
    const float* wt[2] = {nullptr, nullptr};
    int nwt = 0;
    for (int i = 0; i < n_in && nwt < 2; i++)
        if (i != hi) wt[nwt++] = (const float*)d_in[i];
    const float* W   = wt[0];
    const float* tau = (wt[1] != nullptr) ? wt[1] : wt[0];

    float* out = (float*)d_out;

    unsigned long long max_elems = (unsigned long long)out_size;
    const unsigned long long full = (unsigned long long)N_ROWS * M_LEN;
    if (max_elems > full) max_elems = full;

    shiftnmf_fused_kernel<<<GRID, THREADS>>>(H, W, tau, out, max_elems);
}

// round 16
// speedup vs baseline: 1.1739x; 1.1739x over previous
#include <cuda_runtime.h>
#include <cuda_bf16.h>
#include <math_constants.h>

// ShiftNMF fused single-kernel:
//   Phase 1: CTAs 0..15 compute Hft row d = FFT(softplus(H[d,:])) (radix-4,
//            one __sincosf per butterfly, w2 = w1^2), publish via device flag.
//   Phase 2: all CTAs compute out[n,m] =
//            Re( sum_d softplus(W[n,d]) * exp(-2*pi*i*tau[n,d]*m/M) * Hft[d,m] )
//            with the validated FFMA2 Chebyshev rotator loop (LDG-direct).
// Output float32 = Re(V), out_size = N*M.

#define N_ROWS 1024
#define RANK   16
#define M_LEN  4096
#define LOG2M  12

__device__ float2   g_Hft[RANK * M_LEN];
__device__ unsigned g_fft_done;    // zero-init; reset by last CTA each run
__device__ unsigned g_reset_ctr;   // zero-init; reset by last CTA each run

__device__ __forceinline__ float softplus_accurate(float x) {
    return (x > 20.0f) ? x : log1pf(expf(x));
}
__device__ __forceinline__ float2 cmul(float2 a, float2 b) {
    return make_float2(a.x * b.x - a.y * b.y, a.x * b.y + a.y * b.x);
}
__device__ __forceinline__ unsigned long long pack2(float lo, float hi) {
    unsigned long long r;
    asm("mov.b64 %0, {%1, %2};" : "=l"(r) : "f"(lo), "f"(hi));
    return r;
}
__device__ __forceinline__ void unpack2(unsigned long long v, float& lo, float& hi) {
    asm("mov.b64 {%0, %1}, %2;" : "=f"(lo), "=f"(hi) : "l"(v));
}
#define FMA2(dst, a, b, c) \
    asm("fma.rn.f32x2 %0, %1, %2, %3;" : "=l"(dst) : "l"(a), "l"(b), "l"(c))

__device__ __forceinline__ unsigned ld_acquire_u32(const unsigned* p) {
    unsigned v;
    asm volatile("ld.global.acquire.gpu.u32 %0, [%1];" : "=r"(v) : "l"(p));
    return v;
}

// ---------------------------------------------------------------------------
#define THREADS 256
#define CHUNK_M 512
#define M_ITERS (CHUNK_M / 32)            // 16
#define ROWS_W  2
#define WARPS_PER_CTA 8
#define ROWS_CTA (WARPS_PER_CTA * ROWS_W) // 16
#define GRID_MX (M_LEN / CHUNK_M)         // 8
#define GRID_NY (N_ROWS / ROWS_CTA)       // 64
#define GRID    (GRID_MX * GRID_NY)       // 512 CTAs
#define TWO_PI  6.28318530717958647692f

__global__ void __launch_bounds__(THREADS, 2) shiftnmf_fused_kernel(
    const float* __restrict__ H,
    const float* __restrict__ W,
    const float* __restrict__ tau,
    float* __restrict__ out,
    unsigned long long max_elems)
{
    __shared__ float2 buf[M_LEN];                // 32 KB (FFT CTAs only)
    __shared__ float4 tb[ROWS_CTA * RANK];       // 4 KB seed table

    const int tid  = threadIdx.x;
    const int lane = tid & 31;
    const int warp = tid >> 5;
    const int bid  = blockIdx.x;

    // ---------------- Phase 1: CTAs 0..15 compute one FFT row each ----------
    if (bid < RANK) {
        const int row = bid;
        // Base-4 digit-reversed load of softplus(H[row, i]).
        for (int i = tid; i < M_LEN; i += THREADS) {
            unsigned r = __brev((unsigned)i) >> (32 - LOG2M);
            r = ((r & 0x555u) << 1) | ((r >> 1) & 0x555u);
            float v = softplus_accurate(H[row * M_LEN + i]);
            buf[r] = make_float2(v, 0.0f);
        }
        __syncthreads();

        // 6 radix-4 stages, 4 butterflies/thread/stage.
        // One __sincosf per butterfly: w1 = e^{-i*a}, w2 = w1^2, w3 = w1*w2.
        #pragma unroll 1
        for (int s = 1; s <= 6; s++) {
            const int q = 1 << (2 * (s - 1));
            const float astep = -TWO_PI / (float)(4 * q);
            #pragma unroll
            for (int jj = 0; jj < (M_LEN / 4) / THREADS; jj++) {
                int j    = jj * THREADS + tid;
                int k    = j & (q - 1);
                int g    = j >> (2 * (s - 1));
                int base = g * (q << 2) + k;

                float s1, c1;
                __sincosf(astep * (float)k, &s1, &c1);
                float2 w1 = make_float2(c1, s1);
                float2 w2 = make_float2(fmaf(c1, c1, -s1 * s1),
                                        2.0f * c1 * s1 * 1.0f);
                // w2 = w1^2 = (c1^2 - s1^2, 2 c1 s1)
                w2.y = 2.0f * c1 * s1;
                float2 w3 = cmul(w1, w2);

                float2 y0 = buf[base];
                float2 y1 = buf[base + q];
                float2 y2 = buf[base + 2 * q];
                float2 y3 = buf[base + 3 * q];

                float2 t1 = cmul(w1, y1);
                float2 t2 = cmul(w2, y2);
                float2 t3 = cmul(w3, y3);

                float2 u0 = make_float2(y0.x + t2.x, y0.y + t2.y);
                float2 u1 = make_float2(y0.x - t2.x, y0.y - t2.y);
                float2 u2 = make_float2(t1.x + t3.x, t1.y + t3.y);
                float2 u3 = make_float2(t1.x - t3.x, t1.y - t3.y);

                buf[base]         = make_float2(u0.x + u2.x, u0.y + u2.y);
                buf[base + 2 * q] = make_float2(u0.x - u2.x, u0.y - u2.y);
                buf[base + q]     = make_float2(u1.x + u3.y, u1.y - u3.x);
                buf[base + 3 * q] = make_float2(u1.x - u3.y, u1.y + u3.x);
            }
            __syncthreads();
        }

        for (int i = tid; i < M_LEN; i += THREADS) {
            g_Hft[row * M_LEN + i] = buf[i];
        }
        __threadfence();          // publish g_Hft stores
        __syncthreads();
        if (tid == 0) atomicAdd(&g_fft_done, 1u);
    }

    // ---------------- Phase 2: every CTA computes a 16-row x 512-m tile -----
    const int mx     = bid & (GRID_MX - 1);
    const int ny     = bid >> 3;
    const int m_base = mx * CHUNK_M;
    const int nblk   = ny * ROWS_CTA;

    // Seed table: 256 entries (16 rows x 16 d), one thread each.
    {
        const int rl = tid >> 4;
        const int d  = tid & 15;
        const int n  = nblk + rl;
        float t  = tau[n * RANK + d];
        float sw = softplus_accurate(W[n * RANK + d]);
        float ss, cs;
        sincospif(-t * (64.0f / (float)M_LEN), &ss, &cs);   // 32-step angle
        tb[rl * RANK + d] = make_float4(sw, -TWO_PI * t / (float)M_LEN, cs, ss);
    }

    // Wait for all 16 FFT rows (producers are in wave 1: bids 0..15).
    if (tid == 0) {
        while (ld_acquire_u32(&g_fft_done) < (unsigned)RANK) {
            __nanosleep(128);
        }
    }
    __syncthreads();   // releases CTA; also publishes tb

    unsigned long long acc2[ROWS_W][M_ITERS];
    #pragma unroll
    for (int r = 0; r < ROWS_W; r++)
        #pragma unroll
        for (int i = 0; i < M_ITERS; i++) acc2[r][i] = 0ULL;

    const float fm0 = (float)(m_base + lane);
    const float2* __restrict__ hp = g_Hft + m_base + lane;

    #pragma unroll 1
    for (int d = 0; d < RANK; d++) {
        // Seed packed rotators (2 rows, this d) from the smem table.
        unsigned long long A2[ROWS_W], B2[ROWS_W], KP2[ROWS_W], KN2[ROWS_W];
        #pragma unroll
        for (int r = 0; r < ROWS_W; r++) {
            float4 e = tb[(warp * ROWS_W + r) * RANK + d];
            float s0, c0;
            __sincosf(e.y * fm0, &s0, &c0);
            float cr = e.x * c0;
            float ci = e.x * s0;
            float k  = e.z + e.z;
            A2[r]  = pack2(cr, ci);
            B2[r]  = pack2(-fmaf(cr, e.z,  ci * e.w),
                            fmaf(cr, e.w, -ci * e.z));
            KP2[r] = pack2(k, k);
            KN2[r] = pack2(-k, -k);
        }

        const float2* __restrict__ hd = hp + d * M_LEN;

        #pragma unroll
        for (int it = 0; it < M_ITERS; it++) {
            unsigned long long h2 =
                *reinterpret_cast<const unsigned long long*>(&hd[it * 32]);
            #pragma unroll
            for (int r = 0; r < ROWS_W; r++) {
                if ((it & 1) == 0) {
                    FMA2(acc2[r][it], A2[r], h2, acc2[r][it]);
                    FMA2(B2[r], KP2[r], A2[r], B2[r]);
                } else {
                    FMA2(acc2[r][it], B2[r], h2, acc2[r][it]);
                    FMA2(A2[r], KN2[r], B2[r], A2[r]);
                }
            }
        }
    }

    #pragma unroll
    for (int r = 0; r < ROWS_W; r++) {
        const unsigned long long row_base =
            (unsigned long long)(nblk + warp * ROWS_W + r) * M_LEN + m_base;
        #pragma unroll
        for (int it = 0; it < M_ITERS; it++) {
            float ax, ay;
            unpack2(acc2[r][it], ax, ay);
            float val = ((it & 2) == 0) ? (ax - ay) : (ay - ax);
            unsigned long long fi = row_base + (unsigned long long)(it * 32 + lane);
            if (fi < max_elems) out[fi] = val;
        }
    }

    // ---------------- Reset flags for the next (graph-replayed) run --------
    __syncthreads();
    if (tid == 0) {
        unsigned prev = atomicAdd(&g_reset_ctr, 1u);
        if (prev == (unsigned)(GRID - 1)) {
            g_fft_done  = 0u;
            g_reset_ctr = 0u;
            __threadfence();
        }
    }
}

// ---------------------------------------------------------------------------
extern "C" void kernel_launch(void* const* d_in, const int* in_sizes, int n_in,
                              void* d_out, int out_size) {
    // H = strictly largest input; remaining two in given order = W, tau_tilde.
    int hi = 0;
    for (int i = 1; i < n_in; i++)
        if (in_sizes[i] > in_sizes[hi]) hi = i;

    const float* H = (const float*)d_in[hi];
    const float* wt[2] = {nullptr, nullptr};
    int nwt = 0;
    for (int i = 0; i < n_in && nwt < 2; i++)
        if (i != hi) wt[nwt++] = (const float*)d_in[i];
    const float* W   = wt[0];
    const float* tau = (wt[1] != nullptr) ? wt[1] : wt[0];

    float* out = (float*)d_out;

    unsigned long long max_elems = (unsigned long long)out_size;
    const unsigned long long full = (unsigned long long)N_ROWS * M_LEN;
    if (max_elems > full) max_elems = full;

    shiftnmf_fused_kernel<<<GRID, THREADS>>>(H, W, tau, out, max_elems);
}

// round 17
// speedup vs baseline: 1.3279x; 1.1311x over previous
#include <cuda_runtime.h>
#include <cuda_bf16.h>
#include <math_constants.h>

// ShiftNMF: out[n,m] = Re( sum_d softplus(W[n,d]) * exp(-2*pi*i*tau[n,d]*m/M) * Hft[d,m] )
// Hft = full FFT of softplus(H). Output float32 = Re(V), out_size = N*M.
// Two kernels: radix-4 FFT prepass + LDG-direct FFMA2 Chebyshev mainloop.

#define N_ROWS 1024
#define RANK   16
#define M_LEN  4096
#define LOG2M  12

__device__ float2 g_Hft[RANK * M_LEN];

__device__ __forceinline__ float softplus_accurate(float x) {
    return (x > 20.0f) ? x : log1pf(expf(x));
}
__device__ __forceinline__ float2 cmul(float2 a, float2 b) {
    return make_float2(a.x * b.x - a.y * b.y, a.x * b.y + a.y * b.x);
}
__device__ __forceinline__ unsigned long long pack2(float lo, float hi) {
    unsigned long long r;
    asm("mov.b64 %0, {%1, %2};" : "=l"(r) : "f"(lo), "f"(hi));
    return r;
}
__device__ __forceinline__ void unpack2(unsigned long long v, float& lo, float& hi) {
    asm("mov.b64 {%0, %1}, %2;" : "=f"(lo), "=f"(hi) : "l"(v));
}
#define FMA2(dst, a, b, c) \
    asm("fma.rn.f32x2 %0, %1, %2, %3;" : "=l"(dst) : "l"(a), "l"(b), "l"(c))

// ---------------------------------------------------------------------------
// Kernel 1: 16 x 4096-pt FFT of softplus(H), radix-4 DIT (validated R10).
// ---------------------------------------------------------------------------
#define FFT_THREADS 1024

__global__ void __launch_bounds__(FFT_THREADS) fft_hft_kernel(const float* __restrict__ H) {
    __shared__ float2 buf[M_LEN];
    __shared__ float2 tw[M_LEN / 2];
    const int row = blockIdx.x;
    const int tid = threadIdx.x;

    for (int j = tid; j < M_LEN / 2; j += FFT_THREADS) {
        float s, c;
        sincospif(-2.0f * (float)j / (float)M_LEN, &s, &c);
        tw[j] = make_float2(c, s);
    }
    for (int i = tid; i < M_LEN; i += FFT_THREADS) {
        unsigned r = __brev((unsigned)i) >> (32 - LOG2M);
        r = ((r & 0x555u) << 1) | ((r >> 1) & 0x555u);
        float v = softplus_accurate(H[row * M_LEN + i]);
        buf[r] = make_float2(v, 0.0f);
    }
    __syncthreads();

    #pragma unroll 1
    for (int s = 1; s <= 6; s++) {
        const int q   = 1 << (2 * (s - 1));
        const int tsh = LOG2M - 2 * s;
        const int k   = tid & (q - 1);
        const int g   = tid >> (2 * (s - 1));
        const int base = g * (q << 2) + k;

        float2 y0 = buf[base];
        float2 y1 = buf[base + q];
        float2 y2 = buf[base + 2 * q];
        float2 y3 = buf[base + 3 * q];

        float2 w1 = tw[k << tsh];
        float2 w2 = tw[(2 * k) << tsh];
        float2 w3 = cmul(w1, w2);

        float2 t1 = cmul(w1, y1);
        float2 t2 = cmul(w2, y2);
        float2 t3 = cmul(w3, y3);

        float2 u0 = make_float2(y0.x + t2.x, y0.y + t2.y);
        float2 u1 = make_float2(y0.x - t2.x, y0.y - t2.y);
        float2 u2 = make_float2(t1.x + t3.x, t1.y + t3.y);
        float2 u3 = make_float2(t1.x - t3.x, t1.y - t3.y);

        buf[base]         = make_float2(u0.x + u2.x, u0.y + u2.y);
        buf[base + 2 * q] = make_float2(u0.x - u2.x, u0.y - u2.y);
        buf[base + q]     = make_float2(u1.x + u3.y, u1.y - u3.x);
        buf[base + 3 * q] = make_float2(u1.x - u3.y, u1.y + u3.x);
        __syncthreads();
    }

    for (int i = tid; i < M_LEN; i += FFT_THREADS) {
        g_Hft[row * M_LEN + i] = buf[i];
    }
}

// ---------------------------------------------------------------------------
// Kernel 2: LDG-direct, zero-barrier mainloop (R14 skeleton), CHUNK_M=512.
// CTA = 128 thr = 4 warps; warp owns 2 n-rows; CTA tile = 8 rows x 512 m.
// d outer: seed 2 rotators (~12 instr each from smem table), then 16
// m-iterations of 1 coalesced LDG.64 (L1-hit after first warp) + 4 FMA2.
// 56 issued instructions per output element — series minimum.
// ---------------------------------------------------------------------------
#define THREADS 128
#define CHUNK_M 512
#define M_ITERS (CHUNK_M / 32)            // 16
#define ROWS_W  2
#define WARPS_PER_CTA 4
#define ROWS_CTA (WARPS_PER_CTA * ROWS_W) // 8
#define TWO_PI 6.28318530717958647692f

__global__ void __launch_bounds__(THREADS, 4) shiftnmf_main_kernel(
    const float* __restrict__ W,
    const float* __restrict__ tau,
    float* __restrict__ out,
    unsigned long long max_elems)
{
    __shared__ float4 tb[ROWS_CTA * RANK];       // 2 KB: (sw, p, cs, ss)

    const int tid    = threadIdx.x;
    const int lane   = tid & 31;
    const int warp   = tid >> 5;
    const int m_base = blockIdx.x * CHUNK_M;
    const int nblk   = blockIdx.y * ROWS_CTA;

    // Seed table: 128 entries (8 rows x 16 d), one thread each.
    {
        const int rl = tid >> 4;
        const int d  = tid & 15;
        const int n  = nblk + rl;
        float t  = tau[n * RANK + d];
        float sw = softplus_accurate(W[n * RANK + d]);
        float ss, cs;
        sincospif(-t * (64.0f / (float)M_LEN), &ss, &cs);   // 32-step angle
        tb[rl * RANK + d] = make_float4(sw, -TWO_PI * t / (float)M_LEN, cs, ss);
    }
    __syncthreads();   // only barrier in the kernel

    unsigned long long acc2[ROWS_W][M_ITERS];
    #pragma unroll
    for (int r = 0; r < ROWS_W; r++)
        #pragma unroll
        for (int i = 0; i < M_ITERS; i++) acc2[r][i] = 0ULL;

    const float fm0 = (float)(m_base + lane);
    const float2* __restrict__ hp = g_Hft + m_base + lane;

    #pragma unroll 1
    for (int d = 0; d < RANK; d++) {
        // Seed packed rotators (2 rows, this d) from the smem table.
        unsigned long long A2[ROWS_W], B2[ROWS_W], KP2[ROWS_W], KN2[ROWS_W];
        #pragma unroll
        for (int r = 0; r < ROWS_W; r++) {
            float4 e = tb[(warp * ROWS_W + r) * RANK + d];
            float s0, c0;
            __sincosf(e.y * fm0, &s0, &c0);
            float cr = e.x * c0;
            float ci = e.x * s0;
            float k  = e.z + e.z;
            A2[r]  = pack2(cr, ci);
            B2[r]  = pack2(-fmaf(cr, e.z,  ci * e.w),
                            fmaf(cr, e.w, -ci * e.z));
            KP2[r] = pack2(k, k);
            KN2[r] = pack2(-k, -k);
        }

        const float2* __restrict__ hd = hp + d * M_LEN;

        #pragma unroll
        for (int it = 0; it < M_ITERS; it++) {
            unsigned long long h2 =
                *reinterpret_cast<const unsigned long long*>(&hd[it * 32]);
            #pragma unroll
            for (int r = 0; r < ROWS_W; r++) {
                if ((it & 1) == 0) {
                    FMA2(acc2[r][it], A2[r], h2, acc2[r][it]);
                    FMA2(B2[r], KP2[r], A2[r], B2[r]);
                } else {
                    FMA2(acc2[r][it], B2[r], h2, acc2[r][it]);
                    FMA2(A2[r], KN2[r], B2[r], A2[r]);
                }
            }
        }
    }

    #pragma unroll
    for (int r = 0; r < ROWS_W; r++) {
        const unsigned long long row_base =
            (unsigned long long)(nblk + warp * ROWS_W + r) * M_LEN + m_base;
        #pragma unroll
        for (int it = 0; it < M_ITERS; it++) {
            float ax, ay;
            unpack2(acc2[r][it], ax, ay);
            float val = ((it & 2) == 0) ? (ax - ay) : (ay - ax);
            unsigned long long fi = row_base + (unsigned long long)(it * 32 + lane);
            if (fi < max_elems) out[fi] = val;
        }
    }
}

// ---------------------------------------------------------------------------
extern "C" void kernel_launch(void* const* d_in, const int* in_sizes, int n_in,
                              void* d_out, int out_size) {
    // H = strictly largest input; remaining two in given order = W, tau_tilde.
    int hi = 0;
    for (int i = 1; i < n_in; i++)
        if (in_sizes[i] > in_sizes[hi]) hi = i;

    const float* H = (const float*)d_in[hi];
    const float* wt[2] = {nullptr, nullptr};
    int nwt = 0;
    for (int i = 0; i < n_in && nwt < 2; i++)
        if (i != hi) wt[nwt++] = (const float*)d_in[i];
    const float* W   = wt[0];
    const float* tau = (wt[1] != nullptr) ? wt[1] : wt[0];

    float* out = (float*)d_out;

    unsigned long long max_elems = (unsigned long long)out_size;
    const unsigned long long full = (unsigned long long)N_ROWS * M_LEN;
    if (max_elems > full) max_elems = full;

    fft_hft_kernel<<<RANK, FFT_THREADS>>>(H);

    dim3 grid(M_LEN / CHUNK_M, N_ROWS / ROWS_CTA);  // (8, 128) = 1024 CTAs
    shiftnmf_main_kernel<<<grid, THREADS>>>(W, tau, out, max_elems);
}